// round 1
// baseline (speedup 1.0000x reference)
#include <cuda_runtime.h>

#define BB 16
#define NN 1024
#define DD 128

// Scratch (no allocations allowed)
__device__ float  g_a[BB * DD];          // per-batch: b1 + nodes[b,n] @ W1_top
__device__ float2 g_logits[BB * NN];     // per-batch per-j logits

// ---------------------------------------------------------------------------
// Kernel 1: a[b][c] = b1[c] + sum_k nodes[b, n_b, k] * W1[k][c]   (top half)
// grid = B blocks, 128 threads
// ---------------------------------------------------------------------------
__global__ void k_a(const float* __restrict__ nodes, const float* __restrict__ W1,
                    const float* __restrict__ b1, const int* __restrict__ num_nodes) {
    int b = blockIdx.x;
    int c = threadIdx.x;
    int n = num_nodes[b];
    __shared__ float snode[DD];
    snode[c] = nodes[((size_t)b * NN + n) * DD + c];
    __syncthreads();
    float acc = b1[c];
#pragma unroll 8
    for (int k = 0; k < DD; k++)
        acc = fmaf(snode[k], W1[k * DD + c], acc);
    g_a[b * DD + c] = acc;
}

// ---------------------------------------------------------------------------
// Kernel 2: logits[b][j] = relu(a_b + nodes[b,j] @ W1_bot) @ W2 + b2
// grid = B * 16 blocks, 256 threads (8 warps x 8 j's = 64 j's per block)
// W1_bot (64KB) cached in dynamic SMEM.
// ---------------------------------------------------------------------------
#define JS_PER_WARP 8
#define WARPS_PER_BLOCK 8
#define JS_PER_BLOCK (JS_PER_WARP * WARPS_PER_BLOCK)   // 64
#define BLOCKS_PER_B (NN / JS_PER_BLOCK)               // 16

extern __shared__ float s_dyn[];

__global__ void k_logits(const float* __restrict__ nodes, const float* __restrict__ W1,
                         const float* __restrict__ W2, const float* __restrict__ b2) {
    float* sW1b  = s_dyn;                    // [128][128]
    float* sa    = sW1b + DD * DD;           // [128]
    float* sW2   = sa + DD;                  // [128*2] row-major (c*2 + o)
    float* snode = sW2 + 2 * DD;             // [8][128] per-warp staging

    int b   = blockIdx.x / BLOCKS_PER_B;
    int blk = blockIdx.x % BLOCKS_PER_B;
    int tid = threadIdx.x;

    // Cooperative load: W1 bottom half (rows D..2D-1), a_b, W2
    const float4* W1b4  = (const float4*)(W1 + DD * DD);
    float4*       sW1b4 = (float4*)sW1b;
    for (int t = tid; t < DD * DD / 4; t += blockDim.x) sW1b4[t] = W1b4[t];
    if (tid < DD)     sa[tid]  = g_a[b * DD + tid];
    if (tid < 2 * DD) sW2[tid] = W2[tid];
    __syncthreads();

    int w = tid >> 5, lane = tid & 31;
    float* mynode = snode + w * DD;
    int j0 = blk * JS_PER_BLOCK + w * JS_PER_WARP;
    const float b2x = b2[0], b2y = b2[1];
    const int c = 4 * lane;

#pragma unroll 1
    for (int jj = 0; jj < JS_PER_WARP; jj++) {
        int j = j0 + jj;
        // stage node row [128 floats] into this warp's smem slot
        float4 nd = ((const float4*)(nodes + ((size_t)b * NN + j) * DD))[lane];
        ((float4*)mynode)[lane] = nd;
        __syncwarp();

        float4 h = ((const float4*)sa)[lane];
#pragma unroll 8
        for (int k = 0; k < DD; k++) {
            float  nk = mynode[k];
            float4 w4 = ((const float4*)(sW1b + k * DD))[lane];
            h.x = fmaf(nk, w4.x, h.x);
            h.y = fmaf(nk, w4.y, h.y);
            h.z = fmaf(nk, w4.z, h.z);
            h.w = fmaf(nk, w4.w, h.w);
        }
        h.x = fmaxf(h.x, 0.f); h.y = fmaxf(h.y, 0.f);
        h.z = fmaxf(h.z, 0.f); h.w = fmaxf(h.w, 0.f);

        // h @ W2 -> (p0, p1); per-lane partial over its 4 channels
        float4 w2a = ((const float4*)sW2)[2 * lane];       // c..c+1 (o=0,1 interleaved)
        float4 w2b = ((const float4*)sW2)[2 * lane + 1];   // c+2..c+3
        float p0 = h.x * w2a.x + h.y * w2a.z + h.z * w2b.x + h.w * w2b.z;
        float p1 = h.x * w2a.y + h.y * w2a.w + h.z * w2b.y + h.w * w2b.w;
#pragma unroll
        for (int off = 16; off; off >>= 1) {
            p0 += __shfl_xor_sync(0xffffffffu, p0, off);
            p1 += __shfl_xor_sync(0xffffffffu, p1, off);
        }
        if (lane == 0) g_logits[b * NN + j] = make_float2(p0 + b2x, p1 + b2y);
        __syncwarp();
    }
}

// ---------------------------------------------------------------------------
// Kernel 3: streaming scatter + gumbel hard-argmax.
// One thread = one float4 = two (i,j) pairs (last dim = 2).
//   s = state, except  s[i,n]=logits[i] (i<=n)  and  s[n,j]=logits[j] (j<=n)
//   probs = one_hot(argmax(s + g))   (ties -> index 0)
// ---------------------------------------------------------------------------
__global__ void k_main(const float4* __restrict__ state4,
                       const float4* __restrict__ gumbel4,
                       const int*    __restrict__ num_nodes,
                       float4* __restrict__ out_s4,
                       float4* __restrict__ out_p4) {
    size_t idx = (size_t)blockIdx.x * blockDim.x + threadIdx.x;
    const size_t TOT4 = (size_t)BB * NN * NN / 2;   // 2 pairs per float4
    if (idx >= TOT4) return;

    size_t p0 = idx << 1;                 // first pair index
    int b = (int)(p0 >> 20);              // N*N = 2^20 pairs per batch
    int i = (int)((p0 >> 10) & (NN - 1));
    int j = (int)(p0 & (NN - 1));         // even; pairs are (i,j) and (i,j+1)
    int n = __ldg(&num_nodes[b]);

    float4 st = state4[idx];
    float4 g  = gumbel4[idx];

    float2 s0 = make_float2(st.x, st.y);
    float2 s1 = make_float2(st.z, st.w);

    // col mask: (i<=n && j==n) -> logits[i]
    if (j == n && i <= n)     s0 = g_logits[b * NN + i];
    if (j + 1 == n && i <= n) s1 = g_logits[b * NN + i];
    // row mask: (i==n && j<=n) -> logits[j]  (applied last, matches reference)
    if (i == n) {
        if (j <= n)     s0 = g_logits[b * NN + j];
        if (j + 1 <= n) s1 = g_logits[b * NN + j + 1];
    }

    float v0x = s0.x + g.x, v0y = s0.y + g.y;
    float v1x = s1.x + g.z, v1y = s1.y + g.w;
    bool a0 = (v0x >= v0y);               // argmax ties -> index 0
    bool a1 = (v1x >= v1y);

    out_s4[idx] = make_float4(s0.x, s0.y, s1.x, s1.y);
    out_p4[idx] = make_float4(a0 ? 1.f : 0.f, a0 ? 0.f : 1.f,
                              a1 ? 1.f : 0.f, a1 ? 0.f : 1.f);
}

// ---------------------------------------------------------------------------
extern "C" void kernel_launch(void* const* d_in, const int* in_sizes, int n_in,
                              void* d_out, int out_size) {
    const float* nodes     = (const float*)d_in[0];
    const float* state     = (const float*)d_in[1];
    const float* W1        = (const float*)d_in[2];
    const float* b1        = (const float*)d_in[3];
    const float* W2        = (const float*)d_in[4];
    const float* b2        = (const float*)d_in[5];
    const int*   num_nodes = (const int*)  d_in[6];
    const float* gumbel    = (const float*)d_in[7];

    float* out = (float*)d_out;
    const size_t TOT4 = (size_t)BB * NN * NN / 2;   // float4 count per output tensor
    float4* out_s4 = (float4*)out;
    float4* out_p4 = (float4*)out + TOT4;           // probs after s

    // 1) per-batch shared term a_b
    k_a<<<BB, DD>>>(nodes, W1, b1, num_nodes);

    // 2) logits for all (b, j)
    size_t smem = (size_t)(DD * DD + DD + 2 * DD + WARPS_PER_BLOCK * DD) * sizeof(float);
    cudaFuncSetAttribute(k_logits, cudaFuncAttributeMaxDynamicSharedMemorySize, (int)smem);
    k_logits<<<BB * BLOCKS_PER_B, 256, smem>>>(nodes, W1, W2, b2);

    // 3) streaming scatter + gumbel hard-argmax
    unsigned blocks = (unsigned)((TOT4 + 255) / 256);
    k_main<<<blocks, 256>>>((const float4*)state, (const float4*)gumbel,
                            num_nodes, out_s4, out_p4);
}

// round 2
// speedup vs baseline: 1.2129x; 1.2129x over previous
#include <cuda_runtime.h>

#define BB 16
#define NN 1024
#define DD 128

// Scratch (no allocations allowed)
__device__ float2 g_logits[BB * NN];     // per-batch per-j logits

// ---------------------------------------------------------------------------
// k_logits: logits[b][j] = relu(a_b + nodes[b,j] @ W1_bot) @ W2 + b2
//   where a_b = b1 + nodes[b, n_b] @ W1_top  (computed in-block, fused)
// grid = B * 16 blocks, 256 threads (8 warps x 8 j's = 64 j's per block)
// W1_bot (64KB) cached in dynamic SMEM; 8-way j register blocking per warp;
// packed fma.rn.f32x2 (FFMA2) for 2x fp32 FMA throughput.
// ---------------------------------------------------------------------------
#define JPW 8
#define WARPS_PER_BLOCK 8
#define JS_PER_BLOCK (JPW * WARPS_PER_BLOCK)   // 64
#define BLOCKS_PER_B (NN / JS_PER_BLOCK)       // 16

// smem layout (floats):
//   sW1b   [16384]  W1 bottom half
//   sa     [128]    a_b
//   sW2    [256]
//   sprt   [256]    a partials
//   snd    [128]    nodes[b, n] row
//   snode  [8*8*128] per-warp j staging
#define OFF_SA    (DD * DD)
#define OFF_SW2   (OFF_SA + DD)
#define OFF_SPRT  (OFF_SW2 + 2 * DD)
#define OFF_SND   (OFF_SPRT + 256)
#define OFF_SNODE (OFF_SND + DD)
#define SMEM_FLOATS (OFF_SNODE + WARPS_PER_BLOCK * JPW * DD)

extern __shared__ float s_dyn[];

__global__ __launch_bounds__(256, 2)
void k_logits(const float* __restrict__ nodes, const float* __restrict__ W1,
              const float* __restrict__ b1, const float* __restrict__ W2,
              const float* __restrict__ b2, const int* __restrict__ num_nodes) {
    float* sW1b  = s_dyn;
    float* sa    = s_dyn + OFF_SA;
    float* sW2   = s_dyn + OFF_SW2;
    float* sprt  = s_dyn + OFF_SPRT;
    float* snd   = s_dyn + OFF_SND;
    float* snode = s_dyn + OFF_SNODE;

    int b   = blockIdx.x >> 4;
    int blk = blockIdx.x & 15;
    int tid = threadIdx.x;
    int n   = __ldg(&num_nodes[b]);

    // stage nodes[b, n] row + W2
    if (tid < DD)     snd[tid] = nodes[((size_t)b * NN + n) * DD + tid];
    if (tid < 2 * DD) sW2[tid] = W2[tid];
    __syncthreads();

    // fused a_b partial: c = tid&127, k-half = tid>>7 (reads W1 top from L2)
    {
        int c = tid & (DD - 1), half = tid >> 7;
        float acc = 0.f;
        const float* w = W1 + (size_t)(half * 64) * DD + c;
#pragma unroll 8
        for (int k = 0; k < 64; k++)
            acc = fmaf(snd[half * 64 + k], w[k * DD], acc);
        sprt[tid] = acc;
    }

    // cooperative load: W1 bottom half into smem
    {
        const float4* W1b4  = (const float4*)(W1 + DD * DD);
        float4*       sW1b4 = (float4*)sW1b;
#pragma unroll
        for (int t = tid; t < DD * DD / 4; t += 256) sW1b4[t] = W1b4[t];
    }
    __syncthreads();
    if (tid < DD) sa[tid] = b1[tid] + sprt[tid] + sprt[tid + DD];
    __syncthreads();

    int w = tid >> 5, lane = tid & 31;
    float* mynode = snode + w * JPW * DD;
    int j0 = blk * JS_PER_BLOCK + w * JPW;

    // stage this warp's 8 node rows
#pragma unroll
    for (int jj = 0; jj < JPW; jj++)
        ((float4*)(mynode + jj * DD))[lane] =
            ((const float4*)(nodes + ((size_t)b * NN + (j0 + jj)) * DD))[lane];
    __syncwarp();

    // accumulators: 8 j x 4 channels as 2x packed f32x2 each
    ulonglong2 h[JPW];
    {
        ulonglong2 a2 = ((const ulonglong2*)sa)[lane];
#pragma unroll
        for (int jj = 0; jj < JPW; jj++) h[jj] = a2;
    }

#pragma unroll 4
    for (int k = 0; k < DD; k++) {
        ulonglong2 wv = ((const ulonglong2*)(sW1b + k * DD))[lane];
#pragma unroll
        for (int jj = 0; jj < JPW; jj++) {
            float nk = mynode[jj * DD + k];               // LDS broadcast
            unsigned long long nk2;
            asm("mov.b64 %0, {%1, %1};" : "=l"(nk2) : "f"(nk));
            asm("fma.rn.f32x2 %0, %1, %2, %0;" : "+l"(h[jj].x) : "l"(nk2), "l"(wv.x));
            asm("fma.rn.f32x2 %0, %1, %2, %0;" : "+l"(h[jj].y) : "l"(nk2), "l"(wv.y));
        }
    }

    const float b2x = b2[0], b2y = b2[1];
    float4 w2a = ((const float4*)sW2)[2 * lane];
    float4 w2b = ((const float4*)sW2)[2 * lane + 1];
#pragma unroll
    for (int jj = 0; jj < JPW; jj++) {
        float hx, hy, hz, hw;
        asm("mov.b64 {%0, %1}, %2;" : "=f"(hx), "=f"(hy) : "l"(h[jj].x));
        asm("mov.b64 {%0, %1}, %2;" : "=f"(hz), "=f"(hw) : "l"(h[jj].y));
        hx = fmaxf(hx, 0.f); hy = fmaxf(hy, 0.f);
        hz = fmaxf(hz, 0.f); hw = fmaxf(hw, 0.f);
        float p0 = hx * w2a.x + hy * w2a.z + hz * w2b.x + hw * w2b.z;
        float p1 = hx * w2a.y + hy * w2a.w + hz * w2b.y + hw * w2b.w;
#pragma unroll
        for (int off = 16; off; off >>= 1) {
            p0 += __shfl_xor_sync(0xffffffffu, p0, off);
            p1 += __shfl_xor_sync(0xffffffffu, p1, off);
        }
        if (lane == 0) g_logits[b * NN + j0 + jj] = make_float2(p0 + b2x, p1 + b2y);
    }
}

// ---------------------------------------------------------------------------
// k_main: streaming scatter + gumbel hard-argmax (memory-roofline kernel).
//   s = state, except s[i,n]=logits[i] (i<=n) and s[n,j]=logits[j] (j<=n)
//   probs = one_hot(argmax(s + g))   (ties -> index 0)
// Streaming loads/stores (.cs) — zero reuse, keep L2 clean.
// ---------------------------------------------------------------------------
__global__ void k_main(const float4* __restrict__ state4,
                       const float4* __restrict__ gumbel4,
                       const int*    __restrict__ num_nodes,
                       float4* __restrict__ out_s4,
                       float4* __restrict__ out_p4) {
    size_t idx = (size_t)blockIdx.x * blockDim.x + threadIdx.x;
    const size_t TOT4 = (size_t)BB * NN * NN / 2;   // 2 (i,j) pairs per float4
    if (idx >= TOT4) return;

    size_t p0 = idx << 1;
    int b = (int)(p0 >> 20);              // N*N = 2^20 pairs per batch
    int i = (int)((p0 >> 10) & (NN - 1));
    int j = (int)(p0 & (NN - 1));         // even
    int n = __ldg(&num_nodes[b]);

    float4 st = __ldcs(&state4[idx]);
    float4 g  = __ldcs(&gumbel4[idx]);

    float2 s0 = make_float2(st.x, st.y);
    float2 s1 = make_float2(st.z, st.w);

    // col: (i<=n && j==n) -> logits[i]
    if (j == n && i <= n)     s0 = g_logits[b * NN + i];
    if (j + 1 == n && i <= n) s1 = g_logits[b * NN + i];
    // row: (i==n && j<=n) -> logits[j]  (applied last, matches reference)
    if (i == n) {
        if (j <= n)     s0 = g_logits[b * NN + j];
        if (j + 1 <= n) s1 = g_logits[b * NN + j + 1];
    }

    float v0x = s0.x + g.x, v0y = s0.y + g.y;
    float v1x = s1.x + g.z, v1y = s1.y + g.w;
    bool a0 = (v0x >= v0y);               // argmax ties -> index 0
    bool a1 = (v1x >= v1y);

    __stcs(&out_s4[idx], make_float4(s0.x, s0.y, s1.x, s1.y));
    __stcs(&out_p4[idx], make_float4(a0 ? 1.f : 0.f, a0 ? 0.f : 1.f,
                                     a1 ? 1.f : 0.f, a1 ? 0.f : 1.f));
}

// ---------------------------------------------------------------------------
extern "C" void kernel_launch(void* const* d_in, const int* in_sizes, int n_in,
                              void* d_out, int out_size) {
    const float* nodes     = (const float*)d_in[0];
    const float* state     = (const float*)d_in[1];
    const float* W1        = (const float*)d_in[2];
    const float* b1        = (const float*)d_in[3];
    const float* W2        = (const float*)d_in[4];
    const float* b2        = (const float*)d_in[5];
    const int*   num_nodes = (const int*)  d_in[6];
    const float* gumbel    = (const float*)d_in[7];

    float* out = (float*)d_out;
    const size_t TOT4 = (size_t)BB * NN * NN / 2;
    float4* out_s4 = (float4*)out;
    float4* out_p4 = (float4*)out + TOT4;

    // 1) logits for all (b, j) (a_b fused in-block)
    size_t smem = (size_t)SMEM_FLOATS * sizeof(float);
    cudaFuncSetAttribute(k_logits, cudaFuncAttributeMaxDynamicSharedMemorySize, (int)smem);
    k_logits<<<BB * BLOCKS_PER_B, 256, smem>>>(nodes, W1, b1, W2, b2, num_nodes);

    // 2) streaming scatter + gumbel hard-argmax
    unsigned blocks = (unsigned)((TOT4 + 255) / 256);
    k_main<<<blocks, 256>>>((const float4*)state, (const float4*)gumbel,
                            num_nodes, out_s4, out_p4);
}

// round 3
// speedup vs baseline: 1.3420x; 1.1065x over previous
#include <cuda_runtime.h>

#define BB 16
#define NN 1024
#define DD 128

// Scratch (no allocations allowed)
__device__ float2 g_logits[BB * NN];     // per-batch per-j logits (valid for j <= n_b)

// ---------------------------------------------------------------------------
// k_logits: logits[b][j] = relu(a_b + nodes[b,j] @ W1_bot) @ W2 + b2
//   where a_b = b1 + nodes[b, n_b] @ W1_top  (fused in-block)
// Only j <= n_b is ever consumed -> blocks fully above n_b exit immediately.
// ---------------------------------------------------------------------------
#define JPW 8
#define WARPS_PER_BLOCK 8
#define JS_PER_BLOCK (JPW * WARPS_PER_BLOCK)   // 64
#define BLOCKS_PER_B (NN / JS_PER_BLOCK)       // 16

#define OFF_SA    (DD * DD)
#define OFF_SW2   (OFF_SA + DD)
#define OFF_SPRT  (OFF_SW2 + 2 * DD)
#define OFF_SND   (OFF_SPRT + 256)
#define OFF_SNODE (OFF_SND + DD)
#define SMEM_FLOATS (OFF_SNODE + WARPS_PER_BLOCK * JPW * DD)

extern __shared__ float s_dyn[];

__global__ __launch_bounds__(256, 2)
void k_logits(const float* __restrict__ nodes, const float* __restrict__ W1,
              const float* __restrict__ b1, const float* __restrict__ W2,
              const float* __restrict__ b2, const int* __restrict__ num_nodes) {
    float* sW1b  = s_dyn;
    float* sa    = s_dyn + OFF_SA;
    float* sW2   = s_dyn + OFF_SW2;
    float* sprt  = s_dyn + OFF_SPRT;
    float* snd   = s_dyn + OFF_SND;
    float* snode = s_dyn + OFF_SNODE;

    int b   = blockIdx.x >> 4;
    int blk = blockIdx.x & 15;
    int tid = threadIdx.x;
    int n   = __ldg(&num_nodes[b]);
    if (blk * JS_PER_BLOCK > n) return;      // nothing in this block is consumed

    // stage nodes[b, n] row + W2
    if (tid < DD)     snd[tid] = nodes[((size_t)b * NN + n) * DD + tid];
    if (tid < 2 * DD) sW2[tid] = W2[tid];
    __syncthreads();

    // fused a_b partial: c = tid&127, k-half = tid>>7
    {
        int c = tid & (DD - 1), half = tid >> 7;
        float acc = 0.f;
        const float* w = W1 + (size_t)(half * 64) * DD + c;
#pragma unroll 8
        for (int k = 0; k < 64; k++)
            acc = fmaf(snd[half * 64 + k], w[k * DD], acc);
        sprt[tid] = acc;
    }

    // cooperative load: W1 bottom half into smem
    {
        const float4* W1b4  = (const float4*)(W1 + DD * DD);
        float4*       sW1b4 = (float4*)sW1b;
#pragma unroll
        for (int t = tid; t < DD * DD / 4; t += 256) sW1b4[t] = W1b4[t];
    }
    __syncthreads();
    if (tid < DD) sa[tid] = b1[tid] + sprt[tid] + sprt[tid + DD];
    __syncthreads();

    int w = tid >> 5, lane = tid & 31;
    float* mynode = snode + w * JPW * DD;
    int j0 = blk * JS_PER_BLOCK + w * JPW;

#pragma unroll
    for (int jj = 0; jj < JPW; jj++)
        ((float4*)(mynode + jj * DD))[lane] =
            ((const float4*)(nodes + ((size_t)b * NN + (j0 + jj)) * DD))[lane];
    __syncwarp();

    ulonglong2 h[JPW];
    {
        ulonglong2 a2 = ((const ulonglong2*)sa)[lane];
#pragma unroll
        for (int jj = 0; jj < JPW; jj++) h[jj] = a2;
    }

#pragma unroll 4
    for (int k = 0; k < DD; k++) {
        ulonglong2 wv = ((const ulonglong2*)(sW1b + k * DD))[lane];
#pragma unroll
        for (int jj = 0; jj < JPW; jj++) {
            float nk = mynode[jj * DD + k];
            unsigned long long nk2;
            asm("mov.b64 %0, {%1, %1};" : "=l"(nk2) : "f"(nk));
            asm("fma.rn.f32x2 %0, %1, %2, %0;" : "+l"(h[jj].x) : "l"(nk2), "l"(wv.x));
            asm("fma.rn.f32x2 %0, %1, %2, %0;" : "+l"(h[jj].y) : "l"(nk2), "l"(wv.y));
        }
    }

    const float b2x = b2[0], b2y = b2[1];
    float4 w2a = ((const float4*)sW2)[2 * lane];
    float4 w2b = ((const float4*)sW2)[2 * lane + 1];
#pragma unroll
    for (int jj = 0; jj < JPW; jj++) {
        float hx, hy, hz, hw;
        asm("mov.b64 {%0, %1}, %2;" : "=f"(hx), "=f"(hy) : "l"(h[jj].x));
        asm("mov.b64 {%0, %1}, %2;" : "=f"(hz), "=f"(hw) : "l"(h[jj].y));
        hx = fmaxf(hx, 0.f); hy = fmaxf(hy, 0.f);
        hz = fmaxf(hz, 0.f); hw = fmaxf(hw, 0.f);
        float p0 = hx * w2a.x + hy * w2a.z + hz * w2b.x + hw * w2b.z;
        float p1 = hx * w2a.y + hy * w2a.w + hz * w2b.y + hw * w2b.w;
#pragma unroll
        for (int off = 16; off; off >>= 1) {
            p0 += __shfl_xor_sync(0xffffffffu, p0, off);
            p1 += __shfl_xor_sync(0xffffffffu, p1, off);
        }
        if (lane == 0) g_logits[b * NN + j0 + jj] = make_float2(p0 + b2x, p1 + b2y);
    }
}

// ---------------------------------------------------------------------------
// k_bulk: pure stream, NO dependence on logits/num_nodes.
//   out_s = state ; out_p = one_hot(argmax(state + g))  (ties -> index 0)
// Affected row/col entries are overwritten by k_fix afterwards.
// Exact grid, zero index math, ILP=2 with front-batched .cs loads.
// ---------------------------------------------------------------------------
#define TOT4  ((size_t)BB * NN * NN / 2)     // float4 count per output tensor
#define HALF4 (TOT4 / 2)

__global__ void k_bulk(const float4* __restrict__ state4,
                       const float4* __restrict__ gumbel4,
                       float4* __restrict__ out_s4,
                       float4* __restrict__ out_p4) {
    size_t idx = (size_t)blockIdx.x * blockDim.x + threadIdx.x;
    size_t idx2 = idx + HALF4;

    float4 st0 = __ldcs(&state4[idx]);
    float4 g0  = __ldcs(&gumbel4[idx]);
    float4 st1 = __ldcs(&state4[idx2]);
    float4 g1  = __ldcs(&gumbel4[idx2]);

    bool a00 = (st0.x + g0.x) >= (st0.y + g0.y);
    bool a01 = (st0.z + g0.z) >= (st0.w + g0.w);
    bool a10 = (st1.x + g1.x) >= (st1.y + g1.y);
    bool a11 = (st1.z + g1.z) >= (st1.w + g1.w);

    __stcs(&out_s4[idx],  st0);
    __stcs(&out_p4[idx],  make_float4(a00 ? 1.f : 0.f, a00 ? 0.f : 1.f,
                                      a01 ? 1.f : 0.f, a01 ? 0.f : 1.f));
    __stcs(&out_s4[idx2], st1);
    __stcs(&out_p4[idx2], make_float4(a10 ? 1.f : 0.f, a10 ? 0.f : 1.f,
                                      a11 ? 1.f : 0.f, a11 ? 0.f : 1.f));
}

// ---------------------------------------------------------------------------
// k_fix: rewrite the scatter-affected entries.
//   col (i, n), i<=n : s=logits[i] ;  row (n, j), j<=n : s=logits[j]
//   (at (n,n) both give logits[n] -> order irrelevant)
// ---------------------------------------------------------------------------
__global__ void k_fix(const float2* __restrict__ g2,
                      const int* __restrict__ num_nodes,
                      float2* __restrict__ out_s2,
                      float2* __restrict__ out_p2) {
    int b = blockIdx.x;
    int n = __ldg(&num_nodes[b]);
    size_t base = (size_t)b << 20;                 // N*N pairs per batch
    for (int i = threadIdx.x; i <= n; i += blockDim.x) {
        float2 lg = g_logits[b * NN + i];
        // column entry (i, n)
        size_t pc = base + ((size_t)i << 10) + n;
        float2 gc = __ldg(&g2[pc]);
        bool ac = (lg.x + gc.x) >= (lg.y + gc.y);
        out_s2[pc] = lg;
        out_p2[pc] = make_float2(ac ? 1.f : 0.f, ac ? 0.f : 1.f);
        // row entry (n, i)
        size_t pr = base + ((size_t)n << 10) + i;
        float2 gr = __ldg(&g2[pr]);
        bool ar = (lg.x + gr.x) >= (lg.y + gr.y);
        out_s2[pr] = lg;
        out_p2[pr] = make_float2(ar ? 1.f : 0.f, ar ? 0.f : 1.f);
    }
}

// ---------------------------------------------------------------------------
// Fork-join resources: created at static init (before any capture; host-side,
// no device-memory allocation in kernel_launch).
// ---------------------------------------------------------------------------
static cudaStream_t g_s2 = nullptr;
static cudaEvent_t  g_ev0 = nullptr, g_ev1 = nullptr;
static struct _HxInit {
    _HxInit() {
        cudaStreamCreateWithFlags(&g_s2, cudaStreamNonBlocking);
        cudaEventCreateWithFlags(&g_ev0, cudaEventDisableTiming);
        cudaEventCreateWithFlags(&g_ev1, cudaEventDisableTiming);
    }
} _hx_init;

extern "C" void kernel_launch(void* const* d_in, const int* in_sizes, int n_in,
                              void* d_out, int out_size) {
    const float* nodes     = (const float*)d_in[0];
    const float* state     = (const float*)d_in[1];
    const float* W1        = (const float*)d_in[2];
    const float* b1        = (const float*)d_in[3];
    const float* W2        = (const float*)d_in[4];
    const float* b2        = (const float*)d_in[5];
    const int*   num_nodes = (const int*)  d_in[6];
    const float* gumbel    = (const float*)d_in[7];

    float* out = (float*)d_out;
    float4* out_s4 = (float4*)out;
    float4* out_p4 = (float4*)out + TOT4;

    size_t smem = (size_t)SMEM_FLOATS * sizeof(float);
    cudaFuncSetAttribute(k_logits, cudaFuncAttributeMaxDynamicSharedMemorySize, (int)smem);

    bool fork = (g_s2 != nullptr) && (g_ev0 != nullptr) && (g_ev1 != nullptr);

    if (fork) {
        // fork: k_logits on side stream, concurrent with k_bulk on main stream
        cudaEventRecord(g_ev0, 0);
        cudaStreamWaitEvent(g_s2, g_ev0, 0);
        k_logits<<<BB * BLOCKS_PER_B, 256, smem, g_s2>>>(nodes, W1, b1, W2, b2, num_nodes);
        cudaEventRecord(g_ev1, g_s2);

        k_bulk<<<(unsigned)(HALF4 / 256), 256>>>((const float4*)state,
                                                 (const float4*)gumbel,
                                                 out_s4, out_p4);
        // join: fixup needs both logits and bulk output
        cudaStreamWaitEvent(0, g_ev1, 0);
        k_fix<<<BB, 256>>>((const float2*)gumbel, num_nodes,
                           (float2*)out_s4, (float2*)out_p4);
    } else {
        // serial fallback (identical work)
        k_logits<<<BB * BLOCKS_PER_B, 256, smem>>>(nodes, W1, b1, W2, b2, num_nodes);
        k_bulk<<<(unsigned)(HALF4 / 256), 256>>>((const float4*)state,
                                                 (const float4*)gumbel,
                                                 out_s4, out_p4);
        k_fix<<<BB, 256>>>((const float2*)gumbel, num_nodes,
                           (float2*)out_s4, (float2*)out_p4);
    }
}